// round 6
// baseline (speedup 1.0000x reference)
#include <cuda_runtime.h>
#include <cuda_bf16.h>
#include <math.h>

// dims: B=2 N=2048 F=1024 H=16 D=64
#define OUTN 4194304ULL            /* start of kv region in d_out */
#define KV1  (OUTN + 4194304ULL)   /* start of kv[1] (v) */

// fp32 scratch
__device__ float g_S[(size_t)32 * 2048 * 2048];   // scores [bh][i][j]
__device__ float g_Q[(size_t)32 * 2048 * 64];     // q (pre-scaled)

// packed bf16x2 planes (pairs along the contraction dim)
__device__ unsigned g_xh[4096 * 512],  g_xl[4096 * 512];
__device__ unsigned g_wqh[3072 * 512], g_wql[3072 * 512];
__device__ unsigned g_woh[1024 * 512], g_wol[1024 * 512];
__device__ unsigned g_qh[32 * 2048 * 32], g_ql[32 * 2048 * 32];
__device__ unsigned g_kh[32 * 2048 * 32], g_kl[32 * 2048 * 32];
__device__ unsigned g_vth[32 * 64 * 1024], g_vtl[32 * 64 * 1024];
__device__ unsigned g_ph[(size_t)32 * 2048 * 1024];   // attn hi plane
__device__ unsigned g_pl[(size_t)32 * 2048 * 1024];   // attn lo plane
__device__ unsigned g_oh[4096 * 512], g_ol[4096 * 512];

// ---------------------------------------------------------------------------
__device__ __forceinline__ void split_pack(float x0, float x1,
                                           unsigned &hi, unsigned &lo)
{
    __nv_bfloat16 h0 = __float2bfloat16(x0), h1 = __float2bfloat16(x1);
    float f0 = __bfloat162float(h0), f1 = __bfloat162float(h1);
    __nv_bfloat16 l0 = __float2bfloat16(x0 - f0), l1 = __float2bfloat16(x1 - f1);
    hi = ((unsigned)__bfloat16_as_ushort(h1) << 16) | (unsigned)__bfloat16_as_ushort(h0);
    lo = ((unsigned)__bfloat16_as_ushort(l1) << 16) | (unsigned)__bfloat16_as_ushort(l0);
}

__device__ __forceinline__ void mma_bf16(float c[4],
                                         unsigned a0, unsigned a1, unsigned a2, unsigned a3,
                                         unsigned b0, unsigned b1)
{
    asm volatile(
        "mma.sync.aligned.m16n8k16.row.col.f32.bf16.bf16.f32 "
        "{%0,%1,%2,%3},{%4,%5,%6,%7},{%8,%9},{%0,%1,%2,%3};\n"
        : "+f"(c[0]), "+f"(c[1]), "+f"(c[2]), "+f"(c[3])
        : "r"(a0), "r"(a1), "r"(a2), "r"(a3), "r"(b0), "r"(b1));
}

__device__ __forceinline__ void ldmA(unsigned r[4], unsigned addr)
{
    asm volatile("ldmatrix.sync.aligned.m8n8.x4.shared.b16 {%0,%1,%2,%3}, [%4];"
                 : "=r"(r[0]), "=r"(r[1]), "=r"(r[2]), "=r"(r[3]) : "r"(addr));
}
__device__ __forceinline__ void ldmB(unsigned &r0, unsigned &r1, unsigned addr)
{
    asm volatile("ldmatrix.sync.aligned.m8n8.x2.shared.b16 {%0,%1}, [%2];"
                 : "=r"(r0), "=r"(r1) : "r"(addr));
}
// lane-dependent ldmatrix source addresses (byte base + u32 row stride)
__device__ __forceinline__ unsigned ldmA_addr(unsigned base, int ldu, int mr0, int kc, int lane)
{
    int row = mr0 + ((lane >> 3) & 1) * 8 + (lane & 7);
    int col = kc + ((lane >> 4) << 2);
    return base + (unsigned)(row * ldu + col) * 4u;
}
__device__ __forceinline__ unsigned ldmB_addr(unsigned base, int ldu, int nr0, int kc, int lane)
{
    int row = nr0 + (lane & 7);
    int col = kc + (((lane >> 3) & 1) << 2);
    return base + (unsigned)(row * ldu + col) * 4u;
}

__device__ __forceinline__ void cpa(unsigned dst, const unsigned* src)
{
    asm volatile("cp.async.cg.shared.global [%0], [%1], 16;" :: "r"(dst), "l"(src));
}
#define CP_COMMIT asm volatile("cp.async.commit_group;")
#define CP_WAIT0  asm volatile("cp.async.wait_group 0;")

// packed fp32x2 helpers
typedef unsigned long long ull;
__device__ __forceinline__ ull f2pk(float x, float y)
{ ull r; asm("mov.b64 %0,{%1,%2};" : "=l"(r) : "f"(x), "f"(y)); return r; }
__device__ __forceinline__ float2 f2up(ull r)
{ float2 v; asm("mov.b64 {%0,%1},%2;" : "=f"(v.x), "=f"(v.y) : "l"(r)); return v; }
__device__ __forceinline__ ull ffma2(ull a, ull b, ull c)
{ ull d; asm("fma.rn.f32x2 %0,%1,%2,%3;" : "=l"(d) : "l"(a), "l"(b), "l"(c)); return d; }

// ---------------------------------------------------------------------------
// pack input tensors: x (2M pairs), wqkv (1.5M), wout (0.5M)
// ---------------------------------------------------------------------------
__global__ __launch_bounds__(256) void k_pack_in(const float* __restrict__ x,
                                                 const float* __restrict__ wq,
                                                 const float* __restrict__ wo)
{
    unsigned i = blockIdx.x * 256 + threadIdx.x;
    unsigned h, l;
    if (i < 2097152u) {
        float2 v = ((const float2*)x)[i];
        split_pack(v.x, v.y, h, l); g_xh[i] = h; g_xl[i] = l;
    } else if (i < 3670016u) {
        unsigned j = i - 2097152u;
        float2 v = ((const float2*)wq)[j];
        split_pack(v.x, v.y, h, l); g_wqh[j] = h; g_wql[j] = l;
    } else if (i < 4194304u) {
        unsigned j = i - 3670016u;
        float2 v = ((const float2*)wo)[j];
        split_pack(v.x, v.y, h, l); g_woh[j] = h; g_wol[j] = l;
    }
}

// ---------------------------------------------------------------------------
// pack q (from g_Q), k (from d_out kv0), v-transposed (from d_out kv1)
// ---------------------------------------------------------------------------
__global__ __launch_bounds__(256) void k_pack_qkv(const float* __restrict__ out)
{
    unsigned i = blockIdx.x * 256 + threadIdx.x;   // 0 .. 6291455
    unsigned h, l;
    if (i < 2097152u) {
        float2 v = ((const float2*)g_Q)[i];
        split_pack(v.x, v.y, h, l); g_qh[i] = h; g_ql[i] = l;
    } else if (i < 4194304u) {
        unsigned j = i - 2097152u;
        float2 v = ((const float2*)(out + OUTN))[j];
        split_pack(v.x, v.y, h, l); g_kh[j] = h; g_kl[j] = l;
    } else {
        unsigned j  = i - 4194304u;                // bh*65536 + d*1024 + jp
        unsigned bh = j >> 16, r = j & 65535u, d = r >> 10, jp = r & 1023u;
        const float* vb = out + KV1 + (size_t)bh * 131072;
        float v0 = vb[(size_t)(2 * jp) * 64 + d];
        float v1 = vb[(size_t)(2 * jp + 1) * 64 + d];
        split_pack(v0, v1, h, l);
        g_vth[j] = h; g_vtl[j] = l;
    }
}

// ---------------------------------------------------------------------------
// Kernel: QKV projection. M=4096, N=3072, Kdim=1024 (512 pairs).
// cp.async double-buffered; ldmatrix fragment feed; 3-term bf16 split.
// smem/stage: Ah Al Bh Bl 2560 u32 each; 2 stages = 81920 B.
// ---------------------------------------------------------------------------
__global__ __launch_bounds__(256, 2) void k_qkv(float* __restrict__ out)
{
    extern __shared__ unsigned sm[];
    const int t = threadIdx.x, warp = t >> 5, lane = t & 31;
    const int wm = warp >> 2, wn = warp & 3;
    const int g = lane >> 2, q = lane & 3;
    const int m0 = blockIdx.y * 128, n0 = blockIdx.x * 128;
    const unsigned smb = (unsigned)__cvta_generic_to_shared(sm);

    float acc[4][4][4];
#pragma unroll
    for (int i = 0; i < 4; i++)
#pragma unroll
        for (int j = 0; j < 4; j++)
#pragma unroll
            for (int c = 0; c < 4; c++) acc[i][j][c] = 0.f;

#define QKV_LOAD(s, ktp)                                                        \
    {                                                                           \
        unsigned base = smb + (s) * 40960;                                      \
        _Pragma("unroll")                                                       \
        for (int i = 0; i < 2; i++) {                                           \
            int c = t + i * 256; int row = c >> 2; int ch = (c & 3) * 4;        \
            unsigned off = (unsigned)(row * 20 + ch) * 4;                       \
            cpa(base + off,         g_xh  + (size_t)(m0 + row) * 512 + (ktp) + ch); \
            cpa(base + 10240 + off, g_xl  + (size_t)(m0 + row) * 512 + (ktp) + ch); \
            cpa(base + 20480 + off, g_wqh + (size_t)(n0 + row) * 512 + (ktp) + ch); \
            cpa(base + 30720 + off, g_wql + (size_t)(n0 + row) * 512 + (ktp) + ch); \
        }                                                                       \
        CP_COMMIT;                                                              \
    }

    QKV_LOAD(0, 0);
    for (int it = 0; it < 32; it++) {
        CP_WAIT0; __syncthreads();
        if (it + 1 < 32) QKV_LOAD((it + 1) & 1, (it + 1) * 16);
        unsigned base = smb + (it & 1) * 40960;
#pragma unroll
        for (int ks = 0; ks < 2; ks++) {
            int kc = ks * 8;
            unsigned ah[4][4], al[4][4];
#pragma unroll
            for (int mi = 0; mi < 4; mi++) {
                ldmA(ah[mi], ldmA_addr(base,         20, wm * 64 + mi * 16, kc, lane));
                ldmA(al[mi], ldmA_addr(base + 10240, 20, wm * 64 + mi * 16, kc, lane));
            }
#pragma unroll
            for (int ni = 0; ni < 4; ni++) {
                unsigned bh0, bh1, bl0, bl1;
                ldmB(bh0, bh1, ldmB_addr(base + 20480, 20, wn * 32 + ni * 8, kc, lane));
                ldmB(bl0, bl1, ldmB_addr(base + 30720, 20, wn * 32 + ni * 8, kc, lane));
#pragma unroll
                for (int mi = 0; mi < 4; mi++) {
                    mma_bf16(acc[mi][ni], ah[mi][0], ah[mi][1], ah[mi][2], ah[mi][3], bh0, bh1);
                    mma_bf16(acc[mi][ni], ah[mi][0], ah[mi][1], ah[mi][2], ah[mi][3], bl0, bl1);
                    mma_bf16(acc[mi][ni], al[mi][0], al[mi][1], al[mi][2], al[mi][3], bh0, bh1);
                }
            }
        }
        __syncthreads();
    }

#pragma unroll
    for (int mi = 0; mi < 4; mi++) {
#pragma unroll
        for (int cc = 0; cc < 2; cc++) {
            int m  = m0 + wm * 64 + mi * 16 + g + cc * 8;
            int bb = m >> 11;
            int n  = m & 2047;
#pragma unroll
            for (int ni = 0; ni < 4; ni++) {
#pragma unroll
                for (int e = 0; e < 2; e++) {
                    int r = n0 + wn * 32 + ni * 8 + q * 2 + e;
                    float v = acc[mi][ni][cc * 2 + e];
                    int h = r / 192, rem = r - h * 192;
                    int d = rem / 3,  c = rem - d * 3;
                    if (c == 0) {
                        g_Q[(((size_t)(bb * 16 + h)) * 2048 + n) * 64 + d] = v * 0.125f;
                    } else {
                        out[OUTN + (((size_t)((c - 1) * 2 + bb) * 16 + h) * 2048 + n) * 64 + d] = v;
                    }
                }
            }
        }
    }
}

// ---------------------------------------------------------------------------
// Kernel: scores per (b,h). 2048x2048, Kdim=64 (32 pairs) — single-shot tiles.
// smem: Qh[128][36] Ql Kh Kl = 73728 B.
// ---------------------------------------------------------------------------
__global__ __launch_bounds__(256, 2) void k_scores()
{
    extern __shared__ unsigned sm[];
    unsigned (*Qh)[36] = (unsigned(*)[36])(sm);
    unsigned (*Ql)[36] = (unsigned(*)[36])(sm + 4608);
    unsigned (*Kh)[36] = (unsigned(*)[36])(sm + 9216);
    unsigned (*Kl)[36] = (unsigned(*)[36])(sm + 13824);

    const int t = threadIdx.x, warp = t >> 5, lane = t & 31;
    const int wm = warp >> 2, wn = warp & 3;
    const int g = lane >> 2, q = lane & 3;
    const int bh = blockIdx.z;
    const int m0 = blockIdx.y * 128, n0 = blockIdx.x * 128;
    const unsigned smb = (unsigned)__cvta_generic_to_shared(sm);

#pragma unroll
    for (int i = 0; i < 4; i++) {
        int c = t + i * 256;
        int row = c >> 3, ch = (c & 7) * 4;
        *(uint4*)&Qh[row][ch] = *(const uint4*)(g_qh + ((size_t)bh * 2048 + m0 + row) * 32 + ch);
        *(uint4*)&Ql[row][ch] = *(const uint4*)(g_ql + ((size_t)bh * 2048 + m0 + row) * 32 + ch);
        *(uint4*)&Kh[row][ch] = *(const uint4*)(g_kh + ((size_t)bh * 2048 + n0 + row) * 32 + ch);
        *(uint4*)&Kl[row][ch] = *(const uint4*)(g_kl + ((size_t)bh * 2048 + n0 + row) * 32 + ch);
    }
    __syncthreads();

    float acc[4][4][4];
#pragma unroll
    for (int i = 0; i < 4; i++)
#pragma unroll
        for (int j = 0; j < 4; j++)
#pragma unroll
            for (int c = 0; c < 4; c++) acc[i][j][c] = 0.f;

#pragma unroll
    for (int ks = 0; ks < 4; ks++) {
        int kc = ks * 8;
        unsigned ah[4][4], al[4][4];
#pragma unroll
        for (int mi = 0; mi < 4; mi++) {
            ldmA(ah[mi], ldmA_addr(smb,         36, wm * 64 + mi * 16, kc, lane));
            ldmA(al[mi], ldmA_addr(smb + 18432, 36, wm * 64 + mi * 16, kc, lane));
        }
#pragma unroll
        for (int ni = 0; ni < 4; ni++) {
            unsigned bh0, bh1, bl0, bl1;
            ldmB(bh0, bh1, ldmB_addr(smb + 36864, 36, wn * 32 + ni * 8, kc, lane));
            ldmB(bl0, bl1, ldmB_addr(smb + 55296, 36, wn * 32 + ni * 8, kc, lane));
#pragma unroll
            for (int mi = 0; mi < 4; mi++) {
                mma_bf16(acc[mi][ni], ah[mi][0], ah[mi][1], ah[mi][2], ah[mi][3], bh0, bh1);
                mma_bf16(acc[mi][ni], ah[mi][0], ah[mi][1], ah[mi][2], ah[mi][3], bl0, bl1);
                mma_bf16(acc[mi][ni], al[mi][0], al[mi][1], al[mi][2], al[mi][3], bh0, bh1);
            }
        }
    }

#pragma unroll
    for (int mi = 0; mi < 4; mi++) {
#pragma unroll
        for (int cc = 0; cc < 2; cc++) {
            int m = m0 + wm * 64 + mi * 16 + g + cc * 8;
            float* Sp = g_S + ((size_t)bh * 2048 + m) * 2048;
#pragma unroll
            for (int ni = 0; ni < 4; ni++) {
                int n = n0 + wn * 32 + ni * 8 + q * 2;
                __stcs((float2*)(Sp + n),
                       make_float2(acc[mi][ni][cc * 2], acc[mi][ni][cc * 2 + 1]));
            }
        }
    }
}

// ---------------------------------------------------------------------------
// Kernel: fused premix + softmax + postmix. One CTA per (b, i).
// f32x2 packed FMA for head mixes; writes packed attn hi+lo planes.
// ---------------------------------------------------------------------------
__global__ __launch_bounds__(1024) void k_mix(const float* __restrict__ wpre,
                                              const float* __restrict__ bpre,
                                              const float* __restrict__ wpost,
                                              const float* __restrict__ bpost)
{
    extern __shared__ float smf[];
    float* S   = smf;                        // 16*2048 f32
    ull*   WaD = (ull*)(smf + 16 * 2048);    // 256 dup-packed
    ull*   WbD = WaD + 256;                  // 256
    ull*   baD = WbD + 256;                  // 16
    ull*   bbD = baD + 16;                   // 16

    const int t  = threadIdx.x;
    const int bi = blockIdx.x;
    const int b  = bi >> 11;
    const int i  = bi & 2047;

    if (t < 256) {
        float wa = wpre[t], wb = wpost[t];
        WaD[t] = f2pk(wa, wa);
        WbD[t] = f2pk(wb, wb);
    }
    if (t < 16) {
        float v0 = bpre[t], v1 = bpost[t];
        baD[t] = f2pk(v0, v0);
        bbD[t] = f2pk(v1, v1);
    }

    // load 16 head rows: 16 rows x 512 float4 = 8192 float4, 1024 threads x 8
#pragma unroll
    for (int it = 0; it < 8; it++) {
        int idx = t + it * 1024;
        int h   = idx >> 9;
        int j4  = (idx & 511) * 4;
        *(float4*)(S + h * 2048 + j4) =
            __ldcs((const float4*)(g_S + (((size_t)(b * 16 + h)) * 2048 + i) * 2048 + j4));
    }
    __syncthreads();

    // premix (packed f32x2, one column pair per thread)
    {
        int j = t * 2;
        ull sv[16];
#pragma unroll
        for (int h = 0; h < 16; h++) {
            float2 v = *(float2*)(S + h * 2048 + j);
            sv[h] = f2pk(v.x, v.y);
        }
#pragma unroll
        for (int gg = 0; gg < 16; gg++) {
            ull a = baD[gg];
#pragma unroll
            for (int h = 0; h < 16; h++) a = ffma2(WaD[gg * 16 + h], sv[h], a);
            *(float2*)(S + gg * 2048 + j) = f2up(a);
        }
    }
    __syncthreads();

    // softmax: warps 0..15 each own one head row
    const int w = t >> 5, lane = t & 31;
    if (w < 16) {
        float* row = S + w * 2048;
        float m = -1e30f;
        for (int j = lane; j < 2048; j += 32) m = fmaxf(m, row[j]);
#pragma unroll
        for (int o = 16; o; o >>= 1) m = fmaxf(m, __shfl_xor_sync(0xffffffffu, m, o));
        float z = 0.f;
        for (int j = lane; j < 2048; j += 32) {
            float e = __expf(row[j] - m);
            row[j] = e;
            z += e;
        }
#pragma unroll
        for (int o = 16; o; o >>= 1) z += __shfl_xor_sync(0xffffffffu, z, o);
        float inv = 1.f / z;
        for (int j = lane; j < 2048; j += 32) row[j] *= inv;
    }
    __syncthreads();

    // postmix (packed f32x2) -> bf16 hi+lo planes
    {
        int jp = t, j = t * 2;
        ull sv[16];
#pragma unroll
        for (int h = 0; h < 16; h++) {
            float2 v = *(float2*)(S + h * 2048 + j);
            sv[h] = f2pk(v.x, v.y);
        }
#pragma unroll
        for (int gg = 0; gg < 16; gg++) {
            ull a = bbD[gg];
#pragma unroll
            for (int h = 0; h < 16; h++) a = ffma2(WbD[gg * 16 + h], sv[h], a);
            float2 v = f2up(a);
            unsigned hh, ll;
            split_pack(v.x, v.y, hh, ll);
            size_t idx = (((size_t)(b * 16 + gg)) * 2048 + i) * 1024 + jp;
            g_ph[idx] = hh;
            g_pl[idx] = ll;
        }
    }
}

// ---------------------------------------------------------------------------
// Kernel: AV per (b,h). O = P @ V, pipelined; 2-term P, 2-term V (3 mma terms).
// smem/stage: Ph(2560) Pl(2560) Vh(1280) Vl(1280) u32 = 30720 B; 2 stages.
// ---------------------------------------------------------------------------
__global__ __launch_bounds__(256, 2) void k_av()
{
    extern __shared__ unsigned sm[];
    const int t = threadIdx.x, warp = t >> 5, lane = t & 31;
    const int wm = warp >> 2, wn = warp & 3;
    const int g = lane >> 2, q = lane & 3;
    const int bh = blockIdx.z;
    const int m0 = blockIdx.y * 128;
    const unsigned smb = (unsigned)__cvta_generic_to_shared(sm);

    float acc[4][2][4];
#pragma unroll
    for (int i = 0; i < 4; i++)
#pragma unroll
        for (int j = 0; j < 2; j++)
#pragma unroll
            for (int c = 0; c < 4; c++) acc[i][j][c] = 0.f;

    const size_t pbase = (size_t)bh * 2048 * 1024;
    const size_t vbase = (size_t)bh * 64 * 1024;

#define AV_LOAD(s, ktp)                                                         \
    {                                                                           \
        unsigned base = smb + (s) * 30720;                                      \
        _Pragma("unroll")                                                       \
        for (int i = 0; i < 2; i++) {                                           \
            int c = t + i * 256; int row = c >> 2; int ch = (c & 3) * 4;        \
            unsigned off = (unsigned)(row * 20 + ch) * 4;                       \
            cpa(base + off,         g_ph + pbase + (size_t)(m0 + row) * 1024 + (ktp) + ch); \
            cpa(base + 10240 + off, g_pl + pbase + (size_t)(m0 + row) * 1024 + (ktp) + ch); \
        }                                                                       \
        {                                                                       \
            int c = t; int row = c >> 2; int ch = (c & 3) * 4;                  \
            unsigned off = (unsigned)(row * 20 + ch) * 4;                       \
            cpa(base + 20480 + off, g_vth + vbase + (size_t)row * 1024 + (ktp) + ch); \
            cpa(base + 25600 + off, g_vtl + vbase + (size_t)row * 1024 + (ktp) + ch); \
        }                                                                       \
        CP_COMMIT;                                                              \
    }

    AV_LOAD(0, 0);
    for (int it = 0; it < 64; it++) {
        CP_WAIT0; __syncthreads();
        if (it + 1 < 64) AV_LOAD((it + 1) & 1, (it + 1) * 16);
        unsigned base = smb + (it & 1) * 30720;
#pragma unroll
        for (int ks = 0; ks < 2; ks++) {
            int kc = ks * 8;
            unsigned ah[4][4], al[4][4];
#pragma unroll
            for (int mi = 0; mi < 4; mi++) {
                ldmA(ah[mi], ldmA_addr(base,         20, wm * 64 + mi * 16, kc, lane));
                ldmA(al[mi], ldmA_addr(base + 10240, 20, wm * 64 + mi * 16, kc, lane));
            }
#pragma unroll
            for (int ni = 0; ni < 2; ni++) {
                unsigned bh0, bh1, bl0, bl1;
                ldmB(bh0, bh1, ldmB_addr(base + 20480, 20, wn * 16 + ni * 8, kc, lane));
                ldmB(bl0, bl1, ldmB_addr(base + 25600, 20, wn * 16 + ni * 8, kc, lane));
#pragma unroll
                for (int mi = 0; mi < 4; mi++) {
                    mma_bf16(acc[mi][ni], ah[mi][0], ah[mi][1], ah[mi][2], ah[mi][3], bh0, bh1);
                    mma_bf16(acc[mi][ni], ah[mi][0], ah[mi][1], ah[mi][2], ah[mi][3], bl0, bl1);
                    mma_bf16(acc[mi][ni], al[mi][0], al[mi][1], al[mi][2], al[mi][3], bh0, bh1);
                }
            }
        }
        __syncthreads();
    }

    const int b = bh >> 4, h = bh & 15;
#pragma unroll
    for (int mi = 0; mi < 4; mi++) {
#pragma unroll
        for (int ni = 0; ni < 2; ni++) {
            int m  = m0 + wm * 64 + mi * 16 + g;
            int dp = h * 32 + wn * 8 + ni * 4 + q;
            unsigned hh, ll;
            split_pack(acc[mi][ni][0], acc[mi][ni][1], hh, ll);
            size_t idx = ((size_t)(b * 2048 + m)) * 512 + dp;
            g_oh[idx] = hh; g_ol[idx] = ll;
            split_pack(acc[mi][ni][2], acc[mi][ni][3], hh, ll);
            idx = ((size_t)(b * 2048 + m + 8)) * 512 + dp;
            g_oh[idx] = hh; g_ol[idx] = ll;
        }
    }
}

// ---------------------------------------------------------------------------
// Kernel: out projection. M=4096, N=1024, Kdim=1024 (512 pairs), pipelined.
// ---------------------------------------------------------------------------
__global__ __launch_bounds__(256, 2) void k_out(float* __restrict__ out)
{
    extern __shared__ unsigned sm[];
    const int t = threadIdx.x, warp = t >> 5, lane = t & 31;
    const int wm = warp >> 2, wn = warp & 3;
    const int g = lane >> 2, q = lane & 3;
    const int m0 = blockIdx.y * 128, n0 = blockIdx.x * 128;
    const unsigned smb = (unsigned)__cvta_generic_to_shared(sm);

    float acc[4][4][4];
#pragma unroll
    for (int i = 0; i < 4; i++)
#pragma unroll
        for (int j = 0; j < 4; j++)
#pragma unroll
            for (int c = 0; c < 4; c++) acc[i][j][c] = 0.f;

#define OUT_LOAD(s, ktp)                                                        \
    {                                                                           \
        unsigned base = smb + (s) * 40960;                                      \
        _Pragma("unroll")                                                       \
        for (int i = 0; i < 2; i++) {                                           \
            int c = t + i * 256; int row = c >> 2; int ch = (c & 3) * 4;        \
            unsigned off = (unsigned)(row * 20 + ch) * 4;                       \
            cpa(base + off,         g_oh  + (size_t)(m0 + row) * 512 + (ktp) + ch); \
            cpa(base + 10240 + off, g_ol  + (size_t)(m0 + row) * 512 + (ktp) + ch); \
            cpa(base + 20480 + off, g_woh + (size_t)(n0 + row) * 512 + (ktp) + ch); \
            cpa(base + 30720 + off, g_wol + (size_t)(n0 + row) * 512 + (ktp) + ch); \
        }                                                                       \
        CP_COMMIT;                                                              \
    }

    OUT_LOAD(0, 0);
    for (int it = 0; it < 32; it++) {
        CP_WAIT0; __syncthreads();
        if (it + 1 < 32) OUT_LOAD((it + 1) & 1, (it + 1) * 16);
        unsigned base = smb + (it & 1) * 40960;
#pragma unroll
        for (int ks = 0; ks < 2; ks++) {
            int kc = ks * 8;
            unsigned ah[4][4], al[4][4];
#pragma unroll
            for (int mi = 0; mi < 4; mi++) {
                ldmA(ah[mi], ldmA_addr(base,         20, wm * 64 + mi * 16, kc, lane));
                ldmA(al[mi], ldmA_addr(base + 10240, 20, wm * 64 + mi * 16, kc, lane));
            }
#pragma unroll
            for (int ni = 0; ni < 4; ni++) {
                unsigned bh0, bh1, bl0, bl1;
                ldmB(bh0, bh1, ldmB_addr(base + 20480, 20, wn * 32 + ni * 8, kc, lane));
                ldmB(bl0, bl1, ldmB_addr(base + 30720, 20, wn * 32 + ni * 8, kc, lane));
#pragma unroll
                for (int mi = 0; mi < 4; mi++) {
                    mma_bf16(acc[mi][ni], ah[mi][0], ah[mi][1], ah[mi][2], ah[mi][3], bh0, bh1);
                    mma_bf16(acc[mi][ni], ah[mi][0], ah[mi][1], ah[mi][2], ah[mi][3], bl0, bl1);
                    mma_bf16(acc[mi][ni], al[mi][0], al[mi][1], al[mi][2], al[mi][3], bh0, bh1);
                }
            }
        }
        __syncthreads();
    }

#pragma unroll
    for (int mi = 0; mi < 4; mi++) {
#pragma unroll
        for (int cc = 0; cc < 2; cc++) {
            int m = m0 + wm * 64 + mi * 16 + g + cc * 8;
            float* Op = out + (size_t)m * 1024;
#pragma unroll
            for (int ni = 0; ni < 4; ni++) {
                int n = n0 + wn * 32 + ni * 8 + q * 2;
                *(float2*)(Op + n) = make_float2(acc[mi][ni][cc * 2],
                                                 acc[mi][ni][cc * 2 + 1]);
            }
        }
    }
}

// ---------------------------------------------------------------------------
extern "C" void kernel_launch(void* const* d_in, const int* in_sizes, int n_in,
                              void* d_out, int out_size)
{
    const float* x     = (const float*)d_in[0];
    const float* wqkv  = (const float*)d_in[1];
    const float* wout  = (const float*)d_in[2];
    const float* wpre  = (const float*)d_in[3];
    const float* bpre  = (const float*)d_in[4];
    const float* wpost = (const float*)d_in[5];
    const float* bpost = (const float*)d_in[6];
    float* out = (float*)d_out;

    const int SMIX = 16 * 2048 * 4 + 256 * 8 * 2 + 16 * 8 * 2;   // 135,424 B

    cudaFuncSetAttribute(k_qkv,    cudaFuncAttributeMaxDynamicSharedMemorySize, 81920);
    cudaFuncSetAttribute(k_scores, cudaFuncAttributeMaxDynamicSharedMemorySize, 73728);
    cudaFuncSetAttribute(k_mix,    cudaFuncAttributeMaxDynamicSharedMemorySize, SMIX);
    cudaFuncSetAttribute(k_av,     cudaFuncAttributeMaxDynamicSharedMemorySize, 61440);
    cudaFuncSetAttribute(k_out,    cudaFuncAttributeMaxDynamicSharedMemorySize, 81920);

    k_pack_in<<<16384, 256>>>(x, wqkv, wout);
    k_qkv<<<dim3(24, 32), 256, 81920>>>(out);
    k_pack_qkv<<<24576, 256>>>(out);
    k_scores<<<dim3(16, 16, 32), 256, 73728>>>();
    k_mix<<<4096, 1024, SMIX>>>(wpre, bpre, wpost, bpost);
    k_av<<<dim3(1, 16, 32), 256, 61440>>>();
    k_out<<<dim3(8, 32), 256, 81920>>>(out);
}

// round 7
// speedup vs baseline: 1.1076x; 1.1076x over previous
#include <cuda_runtime.h>
#include <cuda_fp16.h>
#include <math.h>

// dims: B=2 N=2048 F=1024 H=16 D=64
#define OUTN 4194304ULL            /* start of kv region in d_out */
#define KV1  (OUTN + 4194304ULL)   /* start of kv[1] (v) */

// fp32 scratch
__device__ float g_S[(size_t)32 * 2048 * 2048];   // scores [bh][i][j]
__device__ float g_Q[(size_t)32 * 2048 * 64];     // q (pre-scaled)

// packed fp16x2 planes (pairs along the contraction dim)
// A-side operands: 2-term split (hi+lo). B-side operands: single plane.
__device__ unsigned g_xh[4096 * 512],  g_xl[4096 * 512];
__device__ unsigned g_wqh[3072 * 512];
__device__ unsigned g_woh[1024 * 512];
__device__ unsigned g_qh[32 * 2048 * 32], g_ql[32 * 2048 * 32];
__device__ unsigned g_kh[32 * 2048 * 32];
__device__ unsigned g_vth[32 * 64 * 1024];
__device__ unsigned g_ph[(size_t)32 * 2048 * 1024];   // attn hi plane
__device__ unsigned g_pl[(size_t)32 * 2048 * 1024];   // attn lo plane
__device__ unsigned g_oh[4096 * 512], g_ol[4096 * 512];

// ---------------------------------------------------------------------------
__device__ __forceinline__ void split_pack(float x0, float x1,
                                           unsigned &hi, unsigned &lo)
{
    __half h0 = __float2half_rn(x0), h1 = __float2half_rn(x1);
    float f0 = __half2float(h0), f1 = __half2float(h1);
    __half l0 = __float2half_rn(x0 - f0), l1 = __float2half_rn(x1 - f1);
    hi = ((unsigned)__half_as_ushort(h1) << 16) | (unsigned)__half_as_ushort(h0);
    lo = ((unsigned)__half_as_ushort(l1) << 16) | (unsigned)__half_as_ushort(l0);
}
__device__ __forceinline__ unsigned pk_f16(float x0, float x1)
{
    __half h0 = __float2half_rn(x0), h1 = __float2half_rn(x1);
    return ((unsigned)__half_as_ushort(h1) << 16) | (unsigned)__half_as_ushort(h0);
}

__device__ __forceinline__ void mma_f16(float c[4],
                                        unsigned a0, unsigned a1, unsigned a2, unsigned a3,
                                        unsigned b0, unsigned b1)
{
    asm volatile(
        "mma.sync.aligned.m16n8k16.row.col.f32.f16.f16.f32 "
        "{%0,%1,%2,%3},{%4,%5,%6,%7},{%8,%9},{%0,%1,%2,%3};\n"
        : "+f"(c[0]), "+f"(c[1]), "+f"(c[2]), "+f"(c[3])
        : "r"(a0), "r"(a1), "r"(a2), "r"(a3), "r"(b0), "r"(b1));
}

__device__ __forceinline__ void ldmA(unsigned r[4], unsigned addr)
{
    asm volatile("ldmatrix.sync.aligned.m8n8.x4.shared.b16 {%0,%1,%2,%3}, [%4];"
                 : "=r"(r[0]), "=r"(r[1]), "=r"(r[2]), "=r"(r[3]) : "r"(addr));
}
__device__ __forceinline__ void ldmB(unsigned &r0, unsigned &r1, unsigned addr)
{
    asm volatile("ldmatrix.sync.aligned.m8n8.x2.shared.b16 {%0,%1}, [%2];"
                 : "=r"(r0), "=r"(r1) : "r"(addr));
}
__device__ __forceinline__ unsigned ldmA_addr(unsigned base, int ldu, int mr0, int kc, int lane)
{
    int row = mr0 + ((lane >> 3) & 1) * 8 + (lane & 7);
    int col = kc + ((lane >> 4) << 2);
    return base + (unsigned)(row * ldu + col) * 4u;
}
__device__ __forceinline__ unsigned ldmB_addr(unsigned base, int ldu, int nr0, int kc, int lane)
{
    int row = nr0 + (lane & 7);
    int col = kc + (((lane >> 3) & 1) << 2);
    return base + (unsigned)(row * ldu + col) * 4u;
}

__device__ __forceinline__ void cpa(unsigned dst, const unsigned* src)
{
    asm volatile("cp.async.cg.shared.global [%0], [%1], 16;" :: "r"(dst), "l"(src));
}
#define CP_COMMIT asm volatile("cp.async.commit_group;")
#define CP_WAIT0  asm volatile("cp.async.wait_group 0;")

// packed fp32x2 helpers
typedef unsigned long long ull;
__device__ __forceinline__ ull f2pk(float x, float y)
{ ull r; asm("mov.b64 %0,{%1,%2};" : "=l"(r) : "f"(x), "f"(y)); return r; }
__device__ __forceinline__ float2 f2up(ull r)
{ float2 v; asm("mov.b64 {%0,%1},%2;" : "=f"(v.x), "=f"(v.y) : "l"(r)); return v; }
__device__ __forceinline__ ull ffma2(ull a, ull b, ull c)
{ ull d; asm("fma.rn.f32x2 %0,%1,%2,%3;" : "=l"(d) : "l"(a), "l"(b), "l"(c)); return d; }

// ---------------------------------------------------------------------------
// pack input tensors: x split (2M pairs), wqkv single (1.5M), wout single (0.5M)
// ---------------------------------------------------------------------------
__global__ __launch_bounds__(256) void k_pack_in(const float* __restrict__ x,
                                                 const float* __restrict__ wq,
                                                 const float* __restrict__ wo)
{
    unsigned i = blockIdx.x * 256 + threadIdx.x;
    if (i < 2097152u) {
        float2 v = ((const float2*)x)[i];
        unsigned h, l;
        split_pack(v.x, v.y, h, l); g_xh[i] = h; g_xl[i] = l;
    } else if (i < 3670016u) {
        unsigned j = i - 2097152u;
        float2 v = ((const float2*)wq)[j];
        g_wqh[j] = pk_f16(v.x, v.y);
    } else if (i < 4194304u) {
        unsigned j = i - 3670016u;
        float2 v = ((const float2*)wo)[j];
        g_woh[j] = pk_f16(v.x, v.y);
    }
}

// ---------------------------------------------------------------------------
// pack q split (from g_Q), k single (kv0), v-transposed single (kv1)
// ---------------------------------------------------------------------------
__global__ __launch_bounds__(256) void k_pack_qkv(const float* __restrict__ out)
{
    unsigned i = blockIdx.x * 256 + threadIdx.x;   // 0 .. 6291455
    if (i < 2097152u) {
        float2 v = ((const float2*)g_Q)[i];
        unsigned h, l;
        split_pack(v.x, v.y, h, l); g_qh[i] = h; g_ql[i] = l;
    } else if (i < 4194304u) {
        unsigned j = i - 2097152u;
        float2 v = ((const float2*)(out + OUTN))[j];
        g_kh[j] = pk_f16(v.x, v.y);
    } else {
        unsigned j  = i - 4194304u;                // bh*65536 + d*1024 + jp
        unsigned bh = j >> 16, r = j & 65535u, d = r >> 10, jp = r & 1023u;
        const float* vb = out + KV1 + (size_t)bh * 131072;
        float v0 = vb[(size_t)(2 * jp) * 64 + d];
        float v1 = vb[(size_t)(2 * jp + 1) * 64 + d];
        g_vth[j] = pk_f16(v0, v1);
    }
}

// ---------------------------------------------------------------------------
// Kernel: QKV projection. M=4096, N=3072, Kdim=1024 (512 pairs).
// cp.async double-buffered; 2-term fp16 (x split, wqkv single).
// smem/stage: Ah Al Bh 2560 u32 each = 30720 B; 2 stages = 61440 B.
// ---------------------------------------------------------------------------
__global__ __launch_bounds__(256, 2) void k_qkv(float* __restrict__ out)
{
    extern __shared__ unsigned sm[];
    const int t = threadIdx.x, warp = t >> 5, lane = t & 31;
    const int wm = warp >> 2, wn = warp & 3;
    const int g = lane >> 2, q = lane & 3;
    const int m0 = blockIdx.y * 128, n0 = blockIdx.x * 128;
    const unsigned smb = (unsigned)__cvta_generic_to_shared(sm);

    float acc[4][4][4];
#pragma unroll
    for (int i = 0; i < 4; i++)
#pragma unroll
        for (int j = 0; j < 4; j++)
#pragma unroll
            for (int c = 0; c < 4; c++) acc[i][j][c] = 0.f;

#define QKV_LOAD(s, ktp)                                                        \
    {                                                                           \
        unsigned base = smb + (s) * 30720;                                      \
        _Pragma("unroll")                                                       \
        for (int i = 0; i < 2; i++) {                                           \
            int c = t + i * 256; int row = c >> 2; int ch = (c & 3) * 4;        \
            unsigned off = (unsigned)(row * 20 + ch) * 4;                       \
            cpa(base + off,         g_xh  + (size_t)(m0 + row) * 512 + (ktp) + ch); \
            cpa(base + 10240 + off, g_xl  + (size_t)(m0 + row) * 512 + (ktp) + ch); \
            cpa(base + 20480 + off, g_wqh + (size_t)(n0 + row) * 512 + (ktp) + ch); \
        }                                                                       \
        CP_COMMIT;                                                              \
    }

    QKV_LOAD(0, 0);
    for (int it = 0; it < 32; it++) {
        CP_WAIT0; __syncthreads();
        if (it + 1 < 32) QKV_LOAD((it + 1) & 1, (it + 1) * 16);
        unsigned base = smb + (it & 1) * 30720;
#pragma unroll
        for (int ks = 0; ks < 2; ks++) {
            int kc = ks * 8;
            unsigned ah[4][4], al[4][4];
#pragma unroll
            for (int mi = 0; mi < 4; mi++) {
                ldmA(ah[mi], ldmA_addr(base,         20, wm * 64 + mi * 16, kc, lane));
                ldmA(al[mi], ldmA_addr(base + 10240, 20, wm * 64 + mi * 16, kc, lane));
            }
#pragma unroll
            for (int ni = 0; ni < 4; ni++) {
                unsigned bh0, bh1;
                ldmB(bh0, bh1, ldmB_addr(base + 20480, 20, wn * 32 + ni * 8, kc, lane));
#pragma unroll
                for (int mi = 0; mi < 4; mi++) {
                    mma_f16(acc[mi][ni], ah[mi][0], ah[mi][1], ah[mi][2], ah[mi][3], bh0, bh1);
                    mma_f16(acc[mi][ni], al[mi][0], al[mi][1], al[mi][2], al[mi][3], bh0, bh1);
                }
            }
        }
        __syncthreads();
    }

#pragma unroll
    for (int mi = 0; mi < 4; mi++) {
#pragma unroll
        for (int cc = 0; cc < 2; cc++) {
            int m  = m0 + wm * 64 + mi * 16 + g + cc * 8;
            int bb = m >> 11;
            int n  = m & 2047;
#pragma unroll
            for (int ni = 0; ni < 4; ni++) {
#pragma unroll
                for (int e = 0; e < 2; e++) {
                    int r = n0 + wn * 32 + ni * 8 + q * 2 + e;
                    float v = acc[mi][ni][cc * 2 + e];
                    int h = r / 192, rem = r - h * 192;
                    int d = rem / 3,  c = rem - d * 3;
                    if (c == 0) {
                        g_Q[(((size_t)(bb * 16 + h)) * 2048 + n) * 64 + d] = v * 0.125f;
                    } else {
                        out[OUTN + (((size_t)((c - 1) * 2 + bb) * 16 + h) * 2048 + n) * 64 + d] = v;
                    }
                }
            }
        }
    }
}

// ---------------------------------------------------------------------------
// Kernel: scores per (b,h). 2048x2048, Kdim=64 (32 pairs) — single-shot tiles.
// smem: Qh[128][36] Ql Kh = 55296 B. 2-term fp16.
// ---------------------------------------------------------------------------
__global__ __launch_bounds__(256, 2) void k_scores()
{
    extern __shared__ unsigned sm[];
    unsigned (*Qh)[36] = (unsigned(*)[36])(sm);
    unsigned (*Ql)[36] = (unsigned(*)[36])(sm + 4608);
    unsigned (*Kh)[36] = (unsigned(*)[36])(sm + 9216);

    const int t = threadIdx.x, warp = t >> 5, lane = t & 31;
    const int wm = warp >> 2, wn = warp & 3;
    const int g = lane >> 2, q = lane & 3;
    const int bh = blockIdx.z;
    const int m0 = blockIdx.y * 128, n0 = blockIdx.x * 128;
    const unsigned smb = (unsigned)__cvta_generic_to_shared(sm);

#pragma unroll
    for (int i = 0; i < 4; i++) {
        int c = t + i * 256;
        int row = c >> 3, ch = (c & 7) * 4;
        *(uint4*)&Qh[row][ch] = *(const uint4*)(g_qh + ((size_t)bh * 2048 + m0 + row) * 32 + ch);
        *(uint4*)&Ql[row][ch] = *(const uint4*)(g_ql + ((size_t)bh * 2048 + m0 + row) * 32 + ch);
        *(uint4*)&Kh[row][ch] = *(const uint4*)(g_kh + ((size_t)bh * 2048 + n0 + row) * 32 + ch);
    }
    __syncthreads();

    float acc[4][4][4];
#pragma unroll
    for (int i = 0; i < 4; i++)
#pragma unroll
        for (int j = 0; j < 4; j++)
#pragma unroll
            for (int c = 0; c < 4; c++) acc[i][j][c] = 0.f;

#pragma unroll
    for (int ks = 0; ks < 4; ks++) {
        int kc = ks * 8;
        unsigned ah[4][4], al[4][4];
#pragma unroll
        for (int mi = 0; mi < 4; mi++) {
            ldmA(ah[mi], ldmA_addr(smb,         36, wm * 64 + mi * 16, kc, lane));
            ldmA(al[mi], ldmA_addr(smb + 18432, 36, wm * 64 + mi * 16, kc, lane));
        }
#pragma unroll
        for (int ni = 0; ni < 4; ni++) {
            unsigned bh0, bh1;
            ldmB(bh0, bh1, ldmB_addr(smb + 36864, 36, wn * 32 + ni * 8, kc, lane));
#pragma unroll
            for (int mi = 0; mi < 4; mi++) {
                mma_f16(acc[mi][ni], ah[mi][0], ah[mi][1], ah[mi][2], ah[mi][3], bh0, bh1);
                mma_f16(acc[mi][ni], al[mi][0], al[mi][1], al[mi][2], al[mi][3], bh0, bh1);
            }
        }
    }

#pragma unroll
    for (int mi = 0; mi < 4; mi++) {
#pragma unroll
        for (int cc = 0; cc < 2; cc++) {
            int m = m0 + wm * 64 + mi * 16 + g + cc * 8;
            float* Sp = g_S + ((size_t)bh * 2048 + m) * 2048;
#pragma unroll
            for (int ni = 0; ni < 4; ni++) {
                int n = n0 + wn * 32 + ni * 8 + q * 2;
                __stcs((float2*)(Sp + n),
                       make_float2(acc[mi][ni][cc * 2], acc[mi][ni][cc * 2 + 1]));
            }
        }
    }
}

// ---------------------------------------------------------------------------
// Kernel: fused premix + softmax + postmix. One CTA per (b, i).
// f32x2 packed FMA for head mixes; writes fp16-split attn planes.
// ---------------------------------------------------------------------------
__global__ __launch_bounds__(1024) void k_mix(const float* __restrict__ wpre,
                                              const float* __restrict__ bpre,
                                              const float* __restrict__ wpost,
                                              const float* __restrict__ bpost)
{
    extern __shared__ float smf[];
    float* S   = smf;                        // 16*2048 f32
    ull*   WaD = (ull*)(smf + 16 * 2048);    // 256 dup-packed
    ull*   WbD = WaD + 256;                  // 256
    ull*   baD = WbD + 256;                  // 16
    ull*   bbD = baD + 16;                   // 16

    const int t  = threadIdx.x;
    const int bi = blockIdx.x;
    const int b  = bi >> 11;
    const int i  = bi & 2047;

    if (t < 256) {
        float wa = wpre[t], wb = wpost[t];
        WaD[t] = f2pk(wa, wa);
        WbD[t] = f2pk(wb, wb);
    }
    if (t < 16) {
        float v0 = bpre[t], v1 = bpost[t];
        baD[t] = f2pk(v0, v0);
        bbD[t] = f2pk(v1, v1);
    }

    // load 16 head rows: 16 rows x 512 float4 = 8192 float4, 1024 threads x 8
#pragma unroll
    for (int it = 0; it < 8; it++) {
        int idx = t + it * 1024;
        int h   = idx >> 9;
        int j4  = (idx & 511) * 4;
        *(float4*)(S + h * 2048 + j4) =
            __ldcs((const float4*)(g_S + (((size_t)(b * 16 + h)) * 2048 + i) * 2048 + j4));
    }
    __syncthreads();

    // premix (packed f32x2, one column pair per thread)
    {
        int j = t * 2;
        ull sv[16];
#pragma unroll
        for (int h = 0; h < 16; h++) {
            float2 v = *(float2*)(S + h * 2048 + j);
            sv[h] = f2pk(v.x, v.y);
        }
#pragma unroll
        for (int gg = 0; gg < 16; gg++) {
            ull a = baD[gg];
#pragma unroll
            for (int h = 0; h < 16; h++) a = ffma2(WaD[gg * 16 + h], sv[h], a);
            *(float2*)(S + gg * 2048 + j) = f2up(a);
        }
    }
    __syncthreads();

    // softmax: warps 0..15 each own one head row
    const int w = t >> 5, lane = t & 31;
    if (w < 16) {
        float* row = S + w * 2048;
        float m = -1e30f;
        for (int j = lane; j < 2048; j += 32) m = fmaxf(m, row[j]);
#pragma unroll
        for (int o = 16; o; o >>= 1) m = fmaxf(m, __shfl_xor_sync(0xffffffffu, m, o));
        float z = 0.f;
        for (int j = lane; j < 2048; j += 32) {
            float e = __expf(row[j] - m);
            row[j] = e;
            z += e;
        }
#pragma unroll
        for (int o = 16; o; o >>= 1) z += __shfl_xor_sync(0xffffffffu, z, o);
        float inv = 1.f / z;
        for (int j = lane; j < 2048; j += 32) row[j] *= inv;
    }
    __syncthreads();

    // postmix (packed f32x2) -> fp16 hi+lo planes
    {
        int jp = t, j = t * 2;
        ull sv[16];
#pragma unroll
        for (int h = 0; h < 16; h++) {
            float2 v = *(float2*)(S + h * 2048 + j);
            sv[h] = f2pk(v.x, v.y);
        }
#pragma unroll
        for (int gg = 0; gg < 16; gg++) {
            ull a = bbD[gg];
#pragma unroll
            for (int h = 0; h < 16; h++) a = ffma2(WbD[gg * 16 + h], sv[h], a);
            float2 v = f2up(a);
            unsigned hh, ll;
            split_pack(v.x, v.y, hh, ll);
            size_t idx = (((size_t)(b * 16 + gg)) * 2048 + i) * 1024 + jp;
            g_ph[idx] = hh;
            g_pl[idx] = ll;
        }
    }
}

// ---------------------------------------------------------------------------
// Kernel: AV per (b,h). O = P @ V; P 2-term fp16 split, V single (2 mma terms).
// smem/stage: Ph(2560) Pl(2560) Vh(1280) u32 = 25600 B; 2 stages = 51200 B.
// ---------------------------------------------------------------------------
__global__ __launch_bounds__(256, 2) void k_av()
{
    extern __shared__ unsigned sm[];
    const int t = threadIdx.x, warp = t >> 5, lane = t & 31;
    const int wm = warp >> 2, wn = warp & 3;
    const int g = lane >> 2, q = lane & 3;
    const int bh = blockIdx.z;
    const int m0 = blockIdx.y * 128;
    const unsigned smb = (unsigned)__cvta_generic_to_shared(sm);

    float acc[4][2][4];
#pragma unroll
    for (int i = 0; i < 4; i++)
#pragma unroll
        for (int j = 0; j < 2; j++)
#pragma unroll
            for (int c = 0; c < 4; c++) acc[i][j][c] = 0.f;

    const size_t pbase = (size_t)bh * 2048 * 1024;
    const size_t vbase = (size_t)bh * 64 * 1024;

#define AV_LOAD(s, ktp)                                                         \
    {                                                                           \
        unsigned base = smb + (s) * 25600;                                      \
        _Pragma("unroll")                                                       \
        for (int i = 0; i < 2; i++) {                                           \
            int c = t + i * 256; int row = c >> 2; int ch = (c & 3) * 4;        \
            unsigned off = (unsigned)(row * 20 + ch) * 4;                       \
            cpa(base + off,         g_ph + pbase + (size_t)(m0 + row) * 1024 + (ktp) + ch); \
            cpa(base + 10240 + off, g_pl + pbase + (size_t)(m0 + row) * 1024 + (ktp) + ch); \
        }                                                                       \
        {                                                                       \
            int c = t; int row = c >> 2; int ch = (c & 3) * 4;                  \
            unsigned off = (unsigned)(row * 20 + ch) * 4;                       \
            cpa(base + 20480 + off, g_vth + vbase + (size_t)row * 1024 + (ktp) + ch); \
        }                                                                       \
        CP_COMMIT;                                                              \
    }

    AV_LOAD(0, 0);
    for (int it = 0; it < 64; it++) {
        CP_WAIT0; __syncthreads();
        if (it + 1 < 64) AV_LOAD((it + 1) & 1, (it + 1) * 16);
        unsigned base = smb + (it & 1) * 25600;
#pragma unroll
        for (int ks = 0; ks < 2; ks++) {
            int kc = ks * 8;
            unsigned ah[4][4], al[4][4];
#pragma unroll
            for (int mi = 0; mi < 4; mi++) {
                ldmA(ah[mi], ldmA_addr(base,         20, wm * 64 + mi * 16, kc, lane));
                ldmA(al[mi], ldmA_addr(base + 10240, 20, wm * 64 + mi * 16, kc, lane));
            }
#pragma unroll
            for (int ni = 0; ni < 2; ni++) {
                unsigned bh0, bh1;
                ldmB(bh0, bh1, ldmB_addr(base + 20480, 20, wn * 16 + ni * 8, kc, lane));
#pragma unroll
                for (int mi = 0; mi < 4; mi++) {
                    mma_f16(acc[mi][ni], ah[mi][0], ah[mi][1], ah[mi][2], ah[mi][3], bh0, bh1);
                    mma_f16(acc[mi][ni], al[mi][0], al[mi][1], al[mi][2], al[mi][3], bh0, bh1);
                }
            }
        }
        __syncthreads();
    }

    const int b = bh >> 4, h = bh & 15;
#pragma unroll
    for (int mi = 0; mi < 4; mi++) {
#pragma unroll
        for (int ni = 0; ni < 2; ni++) {
            int m  = m0 + wm * 64 + mi * 16 + g;
            int dp = h * 32 + wn * 8 + ni * 4 + q;
            unsigned hh, ll;
            split_pack(acc[mi][ni][0], acc[mi][ni][1], hh, ll);
            size_t idx = ((size_t)(b * 2048 + m)) * 512 + dp;
            g_oh[idx] = hh; g_ol[idx] = ll;
            split_pack(acc[mi][ni][2], acc[mi][ni][3], hh, ll);
            idx = ((size_t)(b * 2048 + m + 8)) * 512 + dp;
            g_oh[idx] = hh; g_ol[idx] = ll;
        }
    }
}

// ---------------------------------------------------------------------------
// Kernel: out projection. M=4096, N=1024, Kdim=1024 (512 pairs), 2-term fp16.
// smem/stage: Oh Ol Wh 2560 u32 each = 30720 B; 2 stages = 61440 B.
// ---------------------------------------------------------------------------
__global__ __launch_bounds__(256, 2) void k_out(float* __restrict__ out)
{
    extern __shared__ unsigned sm[];
    const int t = threadIdx.x, warp = t >> 5, lane = t & 31;
    const int wm = warp >> 2, wn = warp & 3;
    const int g = lane >> 2, q = lane & 3;
    const int m0 = blockIdx.y * 128, n0 = blockIdx.x * 128;
    const unsigned smb = (unsigned)__cvta_generic_to_shared(sm);

    float acc[4][4][4];
#pragma unroll
    for (int i = 0; i < 4; i++)
#pragma unroll
        for (int j = 0; j < 4; j++)
#pragma unroll
            for (int c = 0; c < 4; c++) acc[i][j][c] = 0.f;

#define OUT_LOAD(s, ktp)                                                        \
    {                                                                           \
        unsigned base = smb + (s) * 30720;                                      \
        _Pragma("unroll")                                                       \
        for (int i = 0; i < 2; i++) {                                           \
            int c = t + i * 256; int row = c >> 2; int ch = (c & 3) * 4;        \
            unsigned off = (unsigned)(row * 20 + ch) * 4;                       \
            cpa(base + off,         g_oh  + (size_t)(m0 + row) * 512 + (ktp) + ch); \
            cpa(base + 10240 + off, g_ol  + (size_t)(m0 + row) * 512 + (ktp) + ch); \
            cpa(base + 20480 + off, g_woh + (size_t)(n0 + row) * 512 + (ktp) + ch); \
        }                                                                       \
        CP_COMMIT;                                                              \
    }

    OUT_LOAD(0, 0);
    for (int it = 0; it < 32; it++) {
        CP_WAIT0; __syncthreads();
        if (it + 1 < 32) OUT_LOAD((it + 1) & 1, (it + 1) * 16);
        unsigned base = smb + (it & 1) * 30720;
#pragma unroll
        for (int ks = 0; ks < 2; ks++) {
            int kc = ks * 8;
            unsigned ah[4][4], al[4][4];
#pragma unroll
            for (int mi = 0; mi < 4; mi++) {
                ldmA(ah[mi], ldmA_addr(base,         20, wm * 64 + mi * 16, kc, lane));
                ldmA(al[mi], ldmA_addr(base + 10240, 20, wm * 64 + mi * 16, kc, lane));
            }
#pragma unroll
            for (int ni = 0; ni < 4; ni++) {
                unsigned bh0, bh1;
                ldmB(bh0, bh1, ldmB_addr(base + 20480, 20, wn * 32 + ni * 8, kc, lane));
#pragma unroll
                for (int mi = 0; mi < 4; mi++) {
                    mma_f16(acc[mi][ni], ah[mi][0], ah[mi][1], ah[mi][2], ah[mi][3], bh0, bh1);
                    mma_f16(acc[mi][ni], al[mi][0], al[mi][1], al[mi][2], al[mi][3], bh0, bh1);
                }
            }
        }
        __syncthreads();
    }

#pragma unroll
    for (int mi = 0; mi < 4; mi++) {
#pragma unroll
        for (int cc = 0; cc < 2; cc++) {
            int m = m0 + wm * 64 + mi * 16 + g + cc * 8;
            float* Op = out + (size_t)m * 1024;
#pragma unroll
            for (int ni = 0; ni < 4; ni++) {
                int n = n0 + wn * 32 + ni * 8 + q * 2;
                *(float2*)(Op + n) = make_float2(acc[mi][ni][cc * 2],
                                                 acc[mi][ni][cc * 2 + 1]);
            }
        }
    }
}

// ---------------------------------------------------------------------------
extern "C" void kernel_launch(void* const* d_in, const int* in_sizes, int n_in,
                              void* d_out, int out_size)
{
    const float* x     = (const float*)d_in[0];
    const float* wqkv  = (const float*)d_in[1];
    const float* wout  = (const float*)d_in[2];
    const float* wpre  = (const float*)d_in[3];
    const float* bpre  = (const float*)d_in[4];
    const float* wpost = (const float*)d_in[5];
    const float* bpost = (const float*)d_in[6];
    float* out = (float*)d_out;

    const int SMIX = 16 * 2048 * 4 + 256 * 8 * 2 + 16 * 8 * 2;   // 135,424 B

    cudaFuncSetAttribute(k_qkv,    cudaFuncAttributeMaxDynamicSharedMemorySize, 61440);
    cudaFuncSetAttribute(k_scores, cudaFuncAttributeMaxDynamicSharedMemorySize, 55296);
    cudaFuncSetAttribute(k_mix,    cudaFuncAttributeMaxDynamicSharedMemorySize, SMIX);
    cudaFuncSetAttribute(k_av,     cudaFuncAttributeMaxDynamicSharedMemorySize, 51200);
    cudaFuncSetAttribute(k_out,    cudaFuncAttributeMaxDynamicSharedMemorySize, 61440);

    k_pack_in<<<16384, 256>>>(x, wqkv, wout);
    k_qkv<<<dim3(24, 32), 256, 61440>>>(out);
    k_pack_qkv<<<24576, 256>>>(out);
    k_scores<<<dim3(16, 16, 32), 256, 55296>>>();
    k_mix<<<4096, 1024, SMIX>>>(wpre, bpre, wpost, bpost);
    k_av<<<dim3(1, 16, 32), 256, 51200>>>();
    k_out<<<dim3(8, 32), 256, 61440>>>(out);
}

// round 10
// speedup vs baseline: 1.3419x; 1.2116x over previous
#include <cuda_runtime.h>
#include <cuda_fp16.h>
#include <math.h>

// dims: B=2 N=2048 F=1024 H=16 D=64
#define OUTN 4194304ULL            /* start of kv region in d_out */
#define KV1  (OUTN + 4194304ULL)   /* start of kv[1] (v) */

// fp32 scratch
__device__ float g_Q[(size_t)32 * 2048 * 64];     // q (pre-scaled)

// packed fp16x2 planes (pairs along contraction / j dim)
__device__ unsigned g_sh[(size_t)32 * 2048 * 1024];   // scores fp16 pairs (256MB)
__device__ unsigned g_xh[4096 * 512],  g_xl[4096 * 512];
__device__ unsigned g_wqh[3072 * 512];
__device__ unsigned g_woh[1024 * 512];
__device__ unsigned g_qh[32 * 2048 * 32], g_ql[32 * 2048 * 32];
__device__ unsigned g_kh[32 * 2048 * 32];
__device__ unsigned g_vth[32 * 64 * 1024];
__device__ unsigned g_ph[(size_t)32 * 2048 * 1024];   // attn fp16 (single plane)
__device__ unsigned g_oh[4096 * 512], g_ol[4096 * 512];

// ---------------------------------------------------------------------------
__device__ __forceinline__ void split_pack(float x0, float x1,
                                           unsigned &hi, unsigned &lo)
{
    __half h0 = __float2half_rn(x0), h1 = __float2half_rn(x1);
    float f0 = __half2float(h0), f1 = __half2float(h1);
    __half l0 = __float2half_rn(x0 - f0), l1 = __float2half_rn(x1 - f1);
    hi = ((unsigned)__half_as_ushort(h1) << 16) | (unsigned)__half_as_ushort(h0);
    lo = ((unsigned)__half_as_ushort(l1) << 16) | (unsigned)__half_as_ushort(l0);
}
__device__ __forceinline__ unsigned pk_f16(float x0, float x1)
{
    __half h0 = __float2half_rn(x0), h1 = __float2half_rn(x1);
    return ((unsigned)__half_as_ushort(h1) << 16) | (unsigned)__half_as_ushort(h0);
}

__device__ __forceinline__ void mma_f16(float c[4],
                                        unsigned a0, unsigned a1, unsigned a2, unsigned a3,
                                        unsigned b0, unsigned b1)
{
    asm volatile(
        "mma.sync.aligned.m16n8k16.row.col.f32.f16.f16.f32 "
        "{%0,%1,%2,%3},{%4,%5,%6,%7},{%8,%9},{%0,%1,%2,%3};\n"
        : "+f"(c[0]), "+f"(c[1]), "+f"(c[2]), "+f"(c[3])
        : "r"(a0), "r"(a1), "r"(a2), "r"(a3), "r"(b0), "r"(b1));
}

__device__ __forceinline__ void ldmA(unsigned r[4], unsigned addr)
{
    asm volatile("ldmatrix.sync.aligned.m8n8.x4.shared.b16 {%0,%1,%2,%3}, [%4];"
                 : "=r"(r[0]), "=r"(r[1]), "=r"(r[2]), "=r"(r[3]) : "r"(addr));
}
__device__ __forceinline__ void ldmB(unsigned &r0, unsigned &r1, unsigned addr)
{
    asm volatile("ldmatrix.sync.aligned.m8n8.x2.shared.b16 {%0,%1}, [%2];"
                 : "=r"(r0), "=r"(r1) : "r"(addr));
}
__device__ __forceinline__ unsigned ldmA_addr(unsigned base, int ldu, int mr0, int kc, int lane)
{
    int row = mr0 + ((lane >> 3) & 1) * 8 + (lane & 7);
    int col = kc + ((lane >> 4) << 2);
    return base + (unsigned)(row * ldu + col) * 4u;
}
__device__ __forceinline__ unsigned ldmB_addr(unsigned base, int ldu, int nr0, int kc, int lane)
{
    int row = nr0 + (lane & 7);
    int col = kc + (((lane >> 3) & 1) << 2);
    return base + (unsigned)(row * ldu + col) * 4u;
}

__device__ __forceinline__ void cpa(unsigned dst, const unsigned* src)
{
    asm volatile("cp.async.cg.shared.global [%0], [%1], 16;" :: "r"(dst), "l"(src));
}
#define CP_COMMIT asm volatile("cp.async.commit_group;")
#define CP_WAIT0  asm volatile("cp.async.wait_group 0;")

// packed fp32x2 helpers
typedef unsigned long long ull;
__device__ __forceinline__ ull f2pk(float x, float y)
{ ull r; asm("mov.b64 %0,{%1,%2};" : "=l"(r) : "f"(x), "f"(y)); return r; }
__device__ __forceinline__ float2 f2up(ull r)
{ float2 v; asm("mov.b64 {%0,%1},%2;" : "=f"(v.x), "=f"(v.y) : "l"(r)); return v; }
__device__ __forceinline__ ull ffma2(ull a, ull b, ull c)
{ ull d; asm("fma.rn.f32x2 %0,%1,%2,%3;" : "=l"(d) : "l"(a), "l"(b), "l"(c)); return d; }

// ---------------------------------------------------------------------------
// pack input tensors: x split (2M pairs), wqkv single (1.5M), wout single (0.5M)
// ---------------------------------------------------------------------------
__global__ __launch_bounds__(256) void k_pack_in(const float* __restrict__ x,
                                                 const float* __restrict__ wq,
                                                 const float* __restrict__ wo)
{
    unsigned i = blockIdx.x * 256 + threadIdx.x;
    if (i < 2097152u) {
        float2 v = ((const float2*)x)[i];
        unsigned h, l;
        split_pack(v.x, v.y, h, l); g_xh[i] = h; g_xl[i] = l;
    } else if (i < 3670016u) {
        unsigned j = i - 2097152u;
        float2 v = ((const float2*)wq)[j];
        g_wqh[j] = pk_f16(v.x, v.y);
    } else if (i < 4194304u) {
        unsigned j = i - 3670016u;
        float2 v = ((const float2*)wo)[j];
        g_woh[j] = pk_f16(v.x, v.y);
    }
}

// ---------------------------------------------------------------------------
// pack q split (from g_Q), k single (kv0), v-transposed single (kv1)
// ---------------------------------------------------------------------------
__global__ __launch_bounds__(256) void k_pack_qkv(const float* __restrict__ out)
{
    unsigned i = blockIdx.x * 256 + threadIdx.x;   // 0 .. 6291455
    if (i < 2097152u) {
        float2 v = ((const float2*)g_Q)[i];
        unsigned h, l;
        split_pack(v.x, v.y, h, l); g_qh[i] = h; g_ql[i] = l;
    } else if (i < 4194304u) {
        unsigned j = i - 2097152u;
        float2 v = ((const float2*)(out + OUTN))[j];
        g_kh[j] = pk_f16(v.x, v.y);
    } else {
        unsigned j  = i - 4194304u;                // bh*65536 + d*1024 + jp
        unsigned bh = j >> 16, r = j & 65535u, d = r >> 10, jp = r & 1023u;
        const float* vb = out + KV1 + (size_t)bh * 131072;
        float v0 = vb[(size_t)(2 * jp) * 64 + d];
        float v1 = vb[(size_t)(2 * jp + 1) * 64 + d];
        g_vth[j] = pk_f16(v0, v1);
    }
}

// ---------------------------------------------------------------------------
// Kernel: QKV projection. M=4096, N=3072, Kdim=1024 (512 pairs).
// cp.async double-buffered; 2-term fp16 (x split, wqkv single).
// ---------------------------------------------------------------------------
__global__ __launch_bounds__(256, 2) void k_qkv(float* __restrict__ out)
{
    extern __shared__ unsigned sm[];
    const int t = threadIdx.x, warp = t >> 5, lane = t & 31;
    const int wm = warp >> 2, wn = warp & 3;
    const int g = lane >> 2, q = lane & 3;
    const int m0 = blockIdx.y * 128, n0 = blockIdx.x * 128;
    const unsigned smb = (unsigned)__cvta_generic_to_shared(sm);

    float acc[4][4][4];
#pragma unroll
    for (int i = 0; i < 4; i++)
#pragma unroll
        for (int j = 0; j < 4; j++)
#pragma unroll
            for (int c = 0; c < 4; c++) acc[i][j][c] = 0.f;

#define QKV_LOAD(s, ktp)                                                        \
    {                                                                           \
        unsigned base = smb + (s) * 30720;                                      \
        _Pragma("unroll")                                                       \
        for (int i = 0; i < 2; i++) {                                           \
            int c = t + i * 256; int row = c >> 2; int ch = (c & 3) * 4;        \
            unsigned off = (unsigned)(row * 20 + ch) * 4;                       \
            cpa(base + off,         g_xh  + (size_t)(m0 + row) * 512 + (ktp) + ch); \
            cpa(base + 10240 + off, g_xl  + (size_t)(m0 + row) * 512 + (ktp) + ch); \
            cpa(base + 20480 + off, g_wqh + (size_t)(n0 + row) * 512 + (ktp) + ch); \
        }                                                                       \
        CP_COMMIT;                                                              \
    }

    QKV_LOAD(0, 0);
    for (int it = 0; it < 32; it++) {
        CP_WAIT0; __syncthreads();
        if (it + 1 < 32) QKV_LOAD((it + 1) & 1, (it + 1) * 16);
        unsigned base = smb + (it & 1) * 30720;
#pragma unroll
        for (int ks = 0; ks < 2; ks++) {
            int kc = ks * 8;
            unsigned ah[4][4], al[4][4];
#pragma unroll
            for (int mi = 0; mi < 4; mi++) {
                ldmA(ah[mi], ldmA_addr(base,         20, wm * 64 + mi * 16, kc, lane));
                ldmA(al[mi], ldmA_addr(base + 10240, 20, wm * 64 + mi * 16, kc, lane));
            }
#pragma unroll
            for (int ni = 0; ni < 4; ni++) {
                unsigned bh0, bh1;
                ldmB(bh0, bh1, ldmB_addr(base + 20480, 20, wn * 32 + ni * 8, kc, lane));
#pragma unroll
                for (int mi = 0; mi < 4; mi++) {
                    mma_f16(acc[mi][ni], ah[mi][0], ah[mi][1], ah[mi][2], ah[mi][3], bh0, bh1);
                    mma_f16(acc[mi][ni], al[mi][0], al[mi][1], al[mi][2], al[mi][3], bh0, bh1);
                }
            }
        }
        __syncthreads();
    }

#pragma unroll
    for (int mi = 0; mi < 4; mi++) {
#pragma unroll
        for (int cc = 0; cc < 2; cc++) {
            int m  = m0 + wm * 64 + mi * 16 + g + cc * 8;
            int bb = m >> 11;
            int n  = m & 2047;
#pragma unroll
            for (int ni = 0; ni < 4; ni++) {
#pragma unroll
                for (int e = 0; e < 2; e++) {
                    int r = n0 + wn * 32 + ni * 8 + q * 2 + e;
                    float v = acc[mi][ni][cc * 2 + e];
                    int h = r / 192, rem = r - h * 192;
                    int d = rem / 3,  c = rem - d * 3;
                    if (c == 0) {
                        g_Q[(((size_t)(bb * 16 + h)) * 2048 + n) * 64 + d] = v * 0.125f;
                    } else {
                        out[OUTN + (((size_t)((c - 1) * 2 + bb) * 16 + h) * 2048 + n) * 64 + d] = v;
                    }
                }
            }
        }
    }
}

// ---------------------------------------------------------------------------
// Kernel: scores per (b,h). 2048x2048, Kdim=64. Writes packed fp16 S pairs.
// smem: Qh[128][36] Ql Kh = 55296 B. 2-term fp16.
// ---------------------------------------------------------------------------
__global__ __launch_bounds__(256, 2) void k_scores()
{
    extern __shared__ unsigned sm[];
    unsigned (*Qh)[36] = (unsigned(*)[36])(sm);
    unsigned (*Ql)[36] = (unsigned(*)[36])(sm + 4608);
    unsigned (*Kh)[36] = (unsigned(*)[36])(sm + 9216);

    const int t = threadIdx.x, warp = t >> 5, lane = t & 31;
    const int wm = warp >> 2, wn = warp & 3;
    const int g = lane >> 2, q = lane & 3;
    const int bh = blockIdx.z;
    const int m0 = blockIdx.y * 128, n0 = blockIdx.x * 128;
    const unsigned smb = (unsigned)__cvta_generic_to_shared(sm);

#pragma unroll
    for (int i = 0; i < 4; i++) {
        int c = t + i * 256;
        int row = c >> 3, ch = (c & 7) * 4;
        *(uint4*)&Qh[row][ch] = *(const uint4*)(g_qh + ((size_t)bh * 2048 + m0 + row) * 32 + ch);
        *(uint4*)&Ql[row][ch] = *(const uint4*)(g_ql + ((size_t)bh * 2048 + m0 + row) * 32 + ch);
        *(uint4*)&Kh[row][ch] = *(const uint4*)(g_kh + ((size_t)bh * 2048 + n0 + row) * 32 + ch);
    }
    __syncthreads();

    float acc[4][4][4];
#pragma unroll
    for (int i = 0; i < 4; i++)
#pragma unroll
        for (int j = 0; j < 4; j++)
#pragma unroll
            for (int c = 0; c < 4; c++) acc[i][j][c] = 0.f;

#pragma unroll
    for (int ks = 0; ks < 4; ks++) {
        int kc = ks * 8;
        unsigned ah[4][4], al[4][4];
#pragma unroll
        for (int mi = 0; mi < 4; mi++) {
            ldmA(ah[mi], ldmA_addr(smb,         36, wm * 64 + mi * 16, kc, lane));
            ldmA(al[mi], ldmA_addr(smb + 18432, 36, wm * 64 + mi * 16, kc, lane));
        }
#pragma unroll
        for (int ni = 0; ni < 4; ni++) {
            unsigned bh0, bh1;
            ldmB(bh0, bh1, ldmB_addr(smb + 36864, 36, wn * 32 + ni * 8, kc, lane));
#pragma unroll
            for (int mi = 0; mi < 4; mi++) {
                mma_f16(acc[mi][ni], ah[mi][0], ah[mi][1], ah[mi][2], ah[mi][3], bh0, bh1);
                mma_f16(acc[mi][ni], al[mi][0], al[mi][1], al[mi][2], al[mi][3], bh0, bh1);
            }
        }
    }

#pragma unroll
    for (int mi = 0; mi < 4; mi++) {
#pragma unroll
        for (int cc = 0; cc < 2; cc++) {
            int m = m0 + wm * 64 + mi * 16 + g + cc * 8;
            unsigned* Sp = g_sh + ((size_t)bh * 2048 + m) * 1024;
#pragma unroll
            for (int ni = 0; ni < 4; ni++) {
                int np = (n0 + wn * 32 + ni * 8) / 2 + q;   // pair index
                __stcs(Sp + np, pk_f16(acc[mi][ni][cc * 2], acc[mi][ni][cc * 2 + 1]));
            }
        }
    }
}

// ---------------------------------------------------------------------------
// Kernel: fused premix + softmax + postmix. One CTA per (b, i).
// Reads fp16 S pairs; f32x2 packed FMA; writes fp16 attn plane (single).
// ---------------------------------------------------------------------------
__global__ __launch_bounds__(1024) void k_mix(const float* __restrict__ wpre,
                                              const float* __restrict__ bpre,
                                              const float* __restrict__ wpost,
                                              const float* __restrict__ bpost)
{
    extern __shared__ float smf[];
    float* S   = smf;                        // 16*2048 f32
    ull*   WaD = (ull*)(smf + 16 * 2048);    // 256 dup-packed
    ull*   WbD = WaD + 256;                  // 256
    ull*   baD = WbD + 256;                  // 16
    ull*   bbD = baD + 16;                   // 16

    const int t  = threadIdx.x;
    const int bi = blockIdx.x;
    const int b  = bi >> 11;
    const int i  = bi & 2047;

    if (t < 256) {
        float wa = wpre[t], wb = wpost[t];
        WaD[t] = f2pk(wa, wa);
        WbD[t] = f2pk(wb, wb);
    }
    if (t < 16) {
        float v0 = bpre[t], v1 = bpost[t];
        baD[t] = f2pk(v0, v0);
        bbD[t] = f2pk(v1, v1);
    }

    // load 16 head rows (fp16 pairs): 16 x 256 uint4 = 4096, 1024 threads x 4
#pragma unroll
    for (int it = 0; it < 4; it++) {
        int idx = t + it * 1024;
        int h   = idx >> 8;
        int u4  = idx & 255;
        uint4 u = __ldcs((const uint4*)(g_sh + (((size_t)(b * 16 + h)) * 2048 + i) * 1024) + u4);
        float2 fa = __half22float2(*(__half2*)&u.x);
        float2 fb = __half22float2(*(__half2*)&u.y);
        float2 fc = __half22float2(*(__half2*)&u.z);
        float2 fd = __half22float2(*(__half2*)&u.w);
        float* dst = S + h * 2048 + u4 * 8;
        *(float4*)dst       = make_float4(fa.x, fa.y, fb.x, fb.y);
        *(float4*)(dst + 4) = make_float4(fc.x, fc.y, fd.x, fd.y);
    }
    __syncthreads();

    // premix (packed f32x2, one column pair per thread)
    {
        int j = t * 2;
        ull sv[16];
#pragma unroll
        for (int h = 0; h < 16; h++) {
            float2 v = *(float2*)(S + h * 2048 + j);
            sv[h] = f2pk(v.x, v.y);
        }
#pragma unroll
        for (int gg = 0; gg < 16; gg++) {
            ull a = baD[gg];
#pragma unroll
            for (int h = 0; h < 16; h++) a = ffma2(WaD[gg * 16 + h], sv[h], a);
            *(float2*)(S + gg * 2048 + j) = f2up(a);
        }
    }
    __syncthreads();

    // softmax: warps 0..15 each own one head row
    const int w = t >> 5, lane = t & 31;
    if (w < 16) {
        float* row = S + w * 2048;
        float m = -1e30f;
        for (int j = lane; j < 2048; j += 32) m = fmaxf(m, row[j]);
#pragma unroll
        for (int o = 16; o; o >>= 1) m = fmaxf(m, __shfl_xor_sync(0xffffffffu, m, o));
        float z = 0.f;
        for (int j = lane; j < 2048; j += 32) {
            float e = __expf(row[j] - m);
            row[j] = e;
            z += e;
        }
#pragma unroll
        for (int o = 16; o; o >>= 1) z += __shfl_xor_sync(0xffffffffu, z, o);
        float inv = 1.f / z;
        for (int j = lane; j < 2048; j += 32) row[j] *= inv;
    }
    __syncthreads();

    // postmix (packed f32x2) -> single fp16 plane
    {
        int jp = t, j = t * 2;
        ull sv[16];
#pragma unroll
        for (int h = 0; h < 16; h++) {
            float2 v = *(float2*)(S + h * 2048 + j);
            sv[h] = f2pk(v.x, v.y);
        }
#pragma unroll
        for (int gg = 0; gg < 16; gg++) {
            ull a = bbD[gg];
#pragma unroll
            for (int h = 0; h < 16; h++) a = ffma2(WbD[gg * 16 + h], sv[h], a);
            float2 v = f2up(a);
            g_ph[(((size_t)(b * 16 + gg)) * 2048 + i) * 1024 + jp] = pk_f16(v.x, v.y);
        }
    }
}

// ---------------------------------------------------------------------------
// Kernel: AV per (b,h). O = P @ V; single-plane P, single-plane V (1 mma term).
// smem/stage: Ph(2560) Vh(1280) u32 = 15360 B; 2 stages = 30720 B.
// ---------------------------------------------------------------------------
__global__ __launch_bounds__(256, 2) void k_av()
{
    extern __shared__ unsigned sm[];
    const int t = threadIdx.x, warp = t >> 5, lane = t & 31;
    const int wm = warp >> 2, wn = warp & 3;
    const int g = lane >> 2, q = lane & 3;
    const int bh = blockIdx.z;
    const int m0 = blockIdx.y * 128;
    const unsigned smb = (unsigned)__cvta_generic_to_shared(sm);

    float acc[4][2][4];
#pragma unroll
    for (int i = 0; i < 4; i++)
#pragma unroll
        for (int j = 0; j < 2; j++)
#pragma unroll
            for (int c = 0; c < 4; c++) acc[i][j][c] = 0.f;

    const size_t pbase = (size_t)bh * 2048 * 1024;
    const size_t vbase = (size_t)bh * 64 * 1024;

#define AV_LOAD(s, ktp)                                                         \
    {                                                                           \
        unsigned base = smb + (s) * 15360;                                      \
        _Pragma("unroll")                                                       \
        for (int i = 0; i < 2; i++) {                                           \
            int c = t + i * 256; int row = c >> 2; int ch = (c & 3) * 4;        \
            unsigned off = (unsigned)(row * 20 + ch) * 4;                       \
            cpa(base + off, g_ph + pbase + (size_t)(m0 + row) * 1024 + (ktp) + ch); \
        }                                                                       \
        {                                                                       \
            int c = t; int row = c >> 2; int ch = (c & 3) * 4;                  \
            unsigned off = (unsigned)(row * 20 + ch) * 4;                       \
            cpa(base + 10240 + off, g_vth + vbase + (size_t)row * 1024 + (ktp) + ch); \
        }                                                                       \
        CP_COMMIT;                                                              \
    }

    AV_LOAD(0, 0);
    for (int it = 0; it < 64; it++) {
        CP_WAIT0; __syncthreads();
        if (it + 1 < 64) AV_LOAD((it + 1) & 1, (it + 1) * 16);
        unsigned base = smb + (it & 1) * 15360;
#pragma unroll
        for (int ks = 0; ks < 2; ks++) {
            int kc = ks * 8;
            unsigned ah[4][4];
#pragma unroll
            for (int mi = 0; mi < 4; mi++)
                ldmA(ah[mi], ldmA_addr(base, 20, wm * 64 + mi * 16, kc, lane));
#pragma unroll
            for (int ni = 0; ni < 2; ni++) {
                unsigned bh0, bh1;
                ldmB(bh0, bh1, ldmB_addr(base + 10240, 20, wn * 16 + ni * 8, kc, lane));
#pragma unroll
                for (int mi = 0; mi < 4; mi++)
                    mma_f16(acc[mi][ni], ah[mi][0], ah[mi][1], ah[mi][2], ah[mi][3], bh0, bh1);
            }
        }
        __syncthreads();
    }

    const int b = bh >> 4, h = bh & 15;
#pragma unroll
    for (int mi = 0; mi < 4; mi++) {
#pragma unroll
        for (int ni = 0; ni < 2; ni++) {
            int m  = m0 + wm * 64 + mi * 16 + g;
            int dp = h * 32 + wn * 8 + ni * 4 + q;
            unsigned hh, ll;
            split_pack(acc[mi][ni][0], acc[mi][ni][1], hh, ll);
            size_t idx = ((size_t)(b * 2048 + m)) * 512 + dp;
            g_oh[idx] = hh; g_ol[idx] = ll;
            split_pack(acc[mi][ni][2], acc[mi][ni][3], hh, ll);
            idx = ((size_t)(b * 2048 + m + 8)) * 512 + dp;
            g_oh[idx] = hh; g_ol[idx] = ll;
        }
    }
}

// ---------------------------------------------------------------------------
// Kernel: out projection. M=4096, N=1024, Kdim=1024 (512 pairs), 2-term fp16.
// ---------------------------------------------------------------------------
__global__ __launch_bounds__(256, 2) void k_out(float* __restrict__ out)
{
    extern __shared__ unsigned sm[];
    const int t = threadIdx.x, warp = t >> 5, lane = t & 31;
    const int wm = warp >> 2, wn = warp & 3;
    const int g = lane >> 2, q = lane & 3;
    const int m0 = blockIdx.y * 128, n0 = blockIdx.x * 128;
    const unsigned smb = (unsigned)__cvta_generic_to_shared(sm);

    float acc[4][4][4];
#pragma unroll
    for (int i = 0; i < 4; i++)
#pragma unroll
        for (int j = 0; j < 4; j++)
#pragma unroll
            for (int c = 0; c < 4; c++) acc[i][j][c] = 0.f;

#define OUT_LOAD(s, ktp)                                                        \
    {                                                                           \
        unsigned base = smb + (s) * 30720;                                      \
        _Pragma("unroll")                                                       \
        for (int i = 0; i < 2; i++) {                                           \
            int c = t + i * 256; int row = c >> 2; int ch = (c & 3) * 4;        \
            unsigned off = (unsigned)(row * 20 + ch) * 4;                       \
            cpa(base + off,         g_oh  + (size_t)(m0 + row) * 512 + (ktp) + ch); \
            cpa(base + 10240 + off, g_ol  + (size_t)(m0 + row) * 512 + (ktp) + ch); \
            cpa(base + 20480 + off, g_woh + (size_t)(n0 + row) * 512 + (ktp) + ch); \
        }                                                                       \
        CP_COMMIT;                                                              \
    }

    OUT_LOAD(0, 0);
    for (int it = 0; it < 32; it++) {
        CP_WAIT0; __syncthreads();
        if (it + 1 < 32) OUT_LOAD((it + 1) & 1, (it + 1) * 16);
        unsigned base = smb + (it & 1) * 30720;
#pragma unroll
        for (int ks = 0; ks < 2; ks++) {
            int kc = ks * 8;
            unsigned ah[4][4], al[4][4];
#pragma unroll
            for (int mi = 0; mi < 4; mi++) {
                ldmA(ah[mi], ldmA_addr(base,         20, wm * 64 + mi * 16, kc, lane));
                ldmA(al[mi], ldmA_addr(base + 10240, 20, wm * 64 + mi * 16, kc, lane));
            }
#pragma unroll
            for (int ni = 0; ni < 4; ni++) {
                unsigned bh0, bh1;
                ldmB(bh0, bh1, ldmB_addr(base + 20480, 20, wn * 32 + ni * 8, kc, lane));
#pragma unroll
                for (int mi = 0; mi < 4; mi++) {
                    mma_f16(acc[mi][ni], ah[mi][0], ah[mi][1], ah[mi][2], ah[mi][3], bh0, bh1);
                    mma_f16(acc[mi][ni], al[mi][0], al[mi][1], al[mi][2], al[mi][3], bh0, bh1);
                }
            }
        }
        __syncthreads();
    }

#pragma unroll
    for (int mi = 0; mi < 4; mi++) {
#pragma unroll
        for (int cc = 0; cc < 2; cc++) {
            int m = m0 + wm * 64 + mi * 16 + g + cc * 8;
            float* Op = out + (size_t)m * 1024;
#pragma unroll
            for (int ni = 0; ni < 4; ni++) {
                int n = n0 + wn * 32 + ni * 8 + q * 2;
                *(float2*)(Op + n) = make_float2(acc[mi][ni][cc * 2],
                                                 acc[mi][ni][cc * 2 + 1]);
            }
        }
    }
}

// ---------------------------------------------------------------------------
extern "C" void kernel_launch(void* const* d_in, const int* in_sizes, int n_in,
                              void* d_out, int out_size)
{
    const float* x     = (const float*)d_in[0];
    const float* wqkv  = (const float*)d_in[1];
    const float* wout  = (const float*)d_in[2];
    const float* wpre  = (const float*)d_in[3];
    const float* bpre  = (const float*)d_in[4];
    const float* wpost = (const float*)d_in[5];
    const float* bpost = (const float*)d_in[6];
    float* out = (float*)d_out;

    const int SMIX = 16 * 2048 * 4 + 256 * 8 * 2 + 16 * 8 * 2;   // 135,424 B

    cudaFuncSetAttribute(k_qkv,    cudaFuncAttributeMaxDynamicSharedMemorySize, 61440);
    cudaFuncSetAttribute(k_scores, cudaFuncAttributeMaxDynamicSharedMemorySize, 55296);
    cudaFuncSetAttribute(k_mix,    cudaFuncAttributeMaxDynamicSharedMemorySize, SMIX);
    cudaFuncSetAttribute(k_av,     cudaFuncAttributeMaxDynamicSharedMemorySize, 30720);
    cudaFuncSetAttribute(k_out,    cudaFuncAttributeMaxDynamicSharedMemorySize, 61440);

    k_pack_in<<<16384, 256>>>(x, wqkv, wout);
    k_qkv<<<dim3(24, 32), 256, 61440>>>(out);
    k_pack_qkv<<<24576, 256>>>(out);
    k_scores<<<dim3(16, 16, 32), 256, 55296>>>();
    k_mix<<<4096, 1024, SMIX>>>(wpre, bpre, wpost, bpost);
    k_av<<<dim3(1, 16, 32), 256, 30720>>>();
    k_out<<<dim3(8, 32), 256, 61440>>>(out);
}